// round 3
// baseline (speedup 1.0000x reference)
#include <cuda_runtime.h>
#include <cstdio>

// ---------------------------------------------------------------------------
// Problem constants
// ---------------------------------------------------------------------------
#define BB   64
#define TT   300
#define BT   (BB * TT)          // 19200
#define CONDD 64
#define OUTD  72
#define HH   1024
#define H2   2048
#define H3   3072

typedef unsigned long long ull;

// ---------------------------------------------------------------------------
// Device scratch (static globals: allocation-free rule)
// ---------------------------------------------------------------------------
__device__ float g_tmpc[BT * 256];        // cond encoder hidden
__device__ float g_tmpm[BT * 256];        // input encoder hidden
__device__ float g_x0[BT * HH];           // encoder output / layer0 input
__device__ float g_y0[BT * H2];           // layer0 output / layer1 input
__device__ float g_y1[BT * H2];           // layer1 output
__device__ float g_gif[BT * H3];          // gi forward  (reused per layer)
__device__ float g_gib[BT * H3];          // gi backward (reused per layer)
__device__ float g_h[2][2][BB * HH];      // [dir][pingpong][b*H]

// ---------------------------------------------------------------------------
// f32x2 helpers (sm_100a packed fp32 FMA: 2x FFMA issue throughput)
// ---------------------------------------------------------------------------
__device__ __forceinline__ ull packdup(float x) {
    ull r;
    asm("mov.b64 %0, {%1, %1};" : "=l"(r) : "f"(x));
    return r;
}
__device__ __forceinline__ void fma2(ull &d, ull a, ull b) {
    asm("fma.rn.f32x2 %0, %1, %2, %0;" : "+l"(d) : "l"(a), "l"(b));
}
__device__ __forceinline__ void unpack2(ull v, float &a, float &b) {
    asm("mov.b64 {%0, %1}, %2;" : "=f"(a), "=f"(b) : "l"(v));
}

// ---------------------------------------------------------------------------
// Generic SGEMM:  C[M,N] = A[M,K] @ W[N,K]^T + bias[N]   (optional leaky 0.2)
// BM=128, BN=128, BK=8, 256 threads, 8x8 microtile via f32x2.
// Requires: M % 128 == 0, N % 128 == 0, K % 8 == 0 (true for all calls here).
// ---------------------------------------------------------------------------
__global__ __launch_bounds__(256)
void sgemm_tn(const float* __restrict__ A, int lda,
              const float* __restrict__ W, int ldw,
              const float* __restrict__ bias,
              float* __restrict__ C, int ldc,
              int K, int leaky)
{
    __shared__ __align__(16) ull   As2[8][132];  // A duplicated pairs, [k][m]
    __shared__ __align__(16) float Bs [8][132];  // W plain,            [k][n]

    const int tid = threadIdx.x;
    const int ty  = tid >> 4;      // 0..15  -> rows ty*4 and 64+ty*4
    const int tx  = tid & 15;      // 0..15  -> cols tx*4 and 64+tx*4
    const int m0  = blockIdx.y * 128;
    const int n0  = blockIdx.x * 128;

    const int arow  = tid >> 1;    // 0..127
    const int apart = tid & 1;     // 0..1 (which float4 of the 8-wide k slab)

    const float* Aptr = A + (size_t)(m0 + arow) * lda + apart * 4;
    const float* Wptr = W + (size_t)(n0 + arow) * ldw + apart * 4;

    const int nt = K >> 3;

    float4 aReg = *(const float4*)Aptr;
    float4 bReg = *(const float4*)Wptr;

    ull acc[8][4];
#pragma unroll
    for (int i = 0; i < 8; i++)
#pragma unroll
        for (int j = 0; j < 4; j++) acc[i][j] = 0ull;

    for (int kt = 0; kt < nt; kt++) {
        // stage current tile into smem
        const int ks = apart * 4;
        As2[ks + 0][arow] = packdup(aReg.x);
        As2[ks + 1][arow] = packdup(aReg.y);
        As2[ks + 2][arow] = packdup(aReg.z);
        As2[ks + 3][arow] = packdup(aReg.w);
        Bs[ks + 0][arow] = bReg.x;
        Bs[ks + 1][arow] = bReg.y;
        Bs[ks + 2][arow] = bReg.z;
        Bs[ks + 3][arow] = bReg.w;
        __syncthreads();

        // prefetch next tile
        if (kt + 1 < nt) {
            aReg = *(const float4*)(Aptr + (kt + 1) * 8);
            bReg = *(const float4*)(Wptr + (kt + 1) * 8);
        }

#pragma unroll
        for (int k = 0; k < 8; k++) {
            ulonglong2 a01 = *(const ulonglong2*)&As2[k][ty * 4];
            ulonglong2 a23 = *(const ulonglong2*)&As2[k][ty * 4 + 2];
            ulonglong2 a45 = *(const ulonglong2*)&As2[k][64 + ty * 4];
            ulonglong2 a67 = *(const ulonglong2*)&As2[k][64 + ty * 4 + 2];
            ulonglong2 bl  = *(const ulonglong2*)&Bs[k][tx * 4];
            ulonglong2 bh  = *(const ulonglong2*)&Bs[k][64 + tx * 4];

            ull av[8] = {a01.x, a01.y, a23.x, a23.y, a45.x, a45.y, a67.x, a67.y};
            ull bv[4] = {bl.x, bl.y, bh.x, bh.y};
#pragma unroll
            for (int i = 0; i < 8; i++)
#pragma unroll
                for (int j = 0; j < 4; j++)
                    fma2(acc[i][j], av[i], bv[j]);
        }
        __syncthreads();
    }

    // epilogue: bias + optional leaky, write C
#pragma unroll
    for (int i = 0; i < 8; i++) {
        const int row = m0 + ((i < 4) ? (ty * 4 + i) : (64 + ty * 4 + (i - 4)));
#pragma unroll
        for (int p = 0; p < 4; p++) {
            const int cbase = n0 + ((p < 2) ? (tx * 4 + 2 * p) : (64 + tx * 4 + 2 * (p - 2)));
            float f0, f1;
            unpack2(acc[i][p], f0, f1);
            f0 += bias[cbase];
            f1 += bias[cbase + 1];
            if (leaky) {
                if (f0 < 0.f) f0 *= 0.2f;
                if (f1 < 0.f) f1 *= 0.2f;
            }
            C[(size_t)row * ldc + cbase]     = f0;
            C[(size_t)row * ldc + cbase + 1] = f1;
        }
    }
}

// ---------------------------------------------------------------------------
// One GRU timestep for both directions of one layer.
// grid = (64, 2): blockIdx.x -> 16-column hidden slice, blockIdx.y -> dir.
// Each block: gh = h_prev[64,1024] @ W_hh[3 gates x 16 cols, 1024]^T, then
// gate math + h update + y write. 256 threads, thread = (4 batches, 1 col).
// ---------------------------------------------------------------------------
__global__ __launch_bounds__(256)
void gru_step(const float* __restrict__ gi_f, const float* __restrict__ gi_b,
              const float* __restrict__ whh_f, const float* __restrict__ whh_b,
              const float* __restrict__ bhh_f, const float* __restrict__ bhh_b,
              const float* __restrict__ hp_f,  const float* __restrict__ hp_b,
              float* __restrict__ hn_f,        float* __restrict__ hn_b,
              float* __restrict__ y, int t)
{
    const int dir = blockIdx.y;
    const float* gi  = dir ? gi_b  : gi_f;
    const float* whh = dir ? whh_b : whh_f;
    const float* bhh = dir ? bhh_b : bhh_f;
    const float* hp  = dir ? hp_b  : hp_f;
    float*       hn  = dir ? hn_b  : hn_f;
    const int t_eff  = dir ? (TT - 1 - t) : t;
    const int j0     = blockIdx.x * 16;

    __shared__ __align__(16) float Hs[32][68];    // [k][b]
    __shared__ ull Wd[3][32][17];                 // duplicated pairs, [gate][k][col]

    const int tid = threadIdx.x;
    const int ty  = tid >> 4;    // 0..15 -> batches ty*4 .. ty*4+3
    const int tx  = tid & 15;    // 0..15 -> column j0+tx

    ull ar[2] = {0ull, 0ull};    // r-gate acc for batch pairs (b0,b1),(b2,b3)
    ull az[2] = {0ull, 0ull};
    ull an[2] = {0ull, 0ull};

    for (int kt = 0; kt < 32; kt++) {
        const int k0 = kt * 32;

        // load h_prev tile [64 batches x 32 k] -> Hs[k][b]
        {
            int b = tid >> 3, kk = tid & 7;
            float4 v = *(const float4*)&hp[b * HH + k0 + kk * 4];
            Hs[kk * 4 + 0][b] = v.x; Hs[kk * 4 + 1][b] = v.y;
            Hs[kk * 4 + 2][b] = v.z; Hs[kk * 4 + 3][b] = v.w;
            b += 32;
            float4 v2 = *(const float4*)&hp[b * HH + k0 + kk * 4];
            Hs[kk * 4 + 0][b] = v2.x; Hs[kk * 4 + 1][b] = v2.y;
            Hs[kk * 4 + 2][b] = v2.z; Hs[kk * 4 + 3][b] = v2.w;
        }
        // load W_hh tile (3 gates x 16 cols x 32 k), duplicated into pairs
        {
            int q = tid;                       // 0..255
#pragma unroll
            for (int rep = 0; rep < 2; rep++) {
                if (q < 384) {
                    int g = q >> 7, r = q & 127, i = r >> 3, kk = r & 7;
                    float4 v = *(const float4*)&whh[(size_t)(g * HH + j0 + i) * HH + k0 + kk * 4];
                    Wd[g][kk * 4 + 0][i] = packdup(v.x);
                    Wd[g][kk * 4 + 1][i] = packdup(v.y);
                    Wd[g][kk * 4 + 2][i] = packdup(v.z);
                    Wd[g][kk * 4 + 3][i] = packdup(v.w);
                }
                q += 256;
            }
        }
        __syncthreads();

#pragma unroll
        for (int k = 0; k < 32; k++) {
            ulonglong2 hv = *(const ulonglong2*)&Hs[k][ty * 4];
            ull wr = Wd[0][k][tx];
            ull wz = Wd[1][k][tx];
            ull wn = Wd[2][k][tx];
            fma2(ar[0], hv.x, wr); fma2(ar[1], hv.y, wr);
            fma2(az[0], hv.x, wz); fma2(az[1], hv.y, wz);
            fma2(an[0], hv.x, wn); fma2(an[1], hv.y, wn);
        }
        __syncthreads();
    }

    const int j = j0 + tx;
    const float br = bhh[j], bz = bhh[HH + j], bn = bhh[2 * HH + j];

    float ghr[4], ghz[4], ghn[4];
    unpack2(ar[0], ghr[0], ghr[1]); unpack2(ar[1], ghr[2], ghr[3]);
    unpack2(az[0], ghz[0], ghz[1]); unpack2(az[1], ghz[2], ghz[3]);
    unpack2(an[0], ghn[0], ghn[1]); unpack2(an[1], ghn[2], ghn[3]);

#pragma unroll
    for (int i = 0; i < 4; i++) {
        const int b = ty * 4 + i;
        const size_t row = (size_t)b * TT + t_eff;
        const float gir = gi[row * H3 + j];
        const float giz = gi[row * H3 + HH + j];
        const float gin = gi[row * H3 + 2 * HH + j];
        const float r = 1.f / (1.f + expf(-(gir + ghr[i] + br)));
        const float z = 1.f / (1.f + expf(-(giz + ghz[i] + bz)));
        const float n = tanhf(gin + r * (ghn[i] + bn));
        const float hprev = hp[b * HH + j];
        const float h = (1.f - z) * n + z * hprev;
        hn[b * HH + j] = h;
        y[row * H2 + dir * HH + j] = h;
    }
}

// ---------------------------------------------------------------------------
// Utility kernels
// ---------------------------------------------------------------------------
__global__ void zero_kernel(float* a, int n) {
    int i = blockIdx.x * blockDim.x + threadIdx.x;
    if (i < n) a[i] = 0.f;
}

__global__ void reduce_mean(const float* __restrict__ y1, float* __restrict__ out) {
    const int b = blockIdx.x;
    const float* p = y1 + (size_t)b * TT * H2;
    float s = 0.f;
    for (int i = threadIdx.x; i < TT * H2; i += blockDim.x) s += p[i];
    __shared__ float sm[256];
    sm[threadIdx.x] = s;
    __syncthreads();
    for (int off = 128; off; off >>= 1) {
        if (threadIdx.x < off) sm[threadIdx.x] += sm[threadIdx.x + off];
        __syncthreads();
    }
    if (threadIdx.x == 0) out[b] = sm[0] * (1.f / (TT * (float)H2));
}

// ---------------------------------------------------------------------------
// Launch
// ---------------------------------------------------------------------------
extern "C" void kernel_launch(void* const* d_in, const int* in_sizes, int n_in,
                              void* d_out, int out_size)
{
    const float* cond    = (const float*)d_in[0];
    const float* input   = (const float*)d_in[1];
    const float* ce_w1   = (const float*)d_in[2];
    const float* ce_b1   = (const float*)d_in[3];
    const float* ce_w2   = (const float*)d_in[4];
    const float* ce_b2   = (const float*)d_in[5];
    const float* me_w1   = (const float*)d_in[6];
    const float* me_b1   = (const float*)d_in[7];
    const float* me_w2   = (const float*)d_in[8];
    const float* me_b2   = (const float*)d_in[9];
    const float* w_ih_l0f = (const float*)d_in[10];
    const float* w_hh_l0f = (const float*)d_in[11];
    const float* b_ih_l0f = (const float*)d_in[12];
    const float* b_hh_l0f = (const float*)d_in[13];
    const float* w_ih_l0b = (const float*)d_in[14];
    const float* w_hh_l0b = (const float*)d_in[15];
    const float* b_ih_l0b = (const float*)d_in[16];
    const float* b_hh_l0b = (const float*)d_in[17];
    const float* w_ih_l1f = (const float*)d_in[18];
    const float* w_hh_l1f = (const float*)d_in[19];
    const float* b_ih_l1f = (const float*)d_in[20];
    const float* b_hh_l1f = (const float*)d_in[21];
    const float* w_ih_l1b = (const float*)d_in[22];
    const float* w_hh_l1b = (const float*)d_in[23];
    const float* b_ih_l1b = (const float*)d_in[24];
    const float* b_hh_l1b = (const float*)d_in[25];
    float* out = (float*)d_out;

    float *tmpc, *tmpm, *x0, *y0, *y1, *gif, *gib, *hbuf;
    cudaGetSymbolAddress((void**)&tmpc, g_tmpc);
    cudaGetSymbolAddress((void**)&tmpm, g_tmpm);
    cudaGetSymbolAddress((void**)&x0,   g_x0);
    cudaGetSymbolAddress((void**)&y0,   g_y0);
    cudaGetSymbolAddress((void**)&y1,   g_y1);
    cudaGetSymbolAddress((void**)&gif,  g_gif);
    cudaGetSymbolAddress((void**)&gib,  g_gib);
    cudaGetSymbolAddress((void**)&hbuf, g_h);

    const dim3 thr(256);
    const int MB = BT / 128;   // 150 m-blocks

    // --- encoders ---
    sgemm_tn<<<dim3(256 / 128, MB), thr>>>(cond,  CONDD, ce_w1, CONDD, ce_b1, tmpc, 256, CONDD, 1);
    sgemm_tn<<<dim3(256 / 128, MB), thr>>>(input, OUTD,  me_w1, OUTD,  me_b1, tmpm, 256, OUTD,  1);
    sgemm_tn<<<dim3(512 / 128, MB), thr>>>(tmpc, 256, ce_w2, 256, ce_b2, x0,        HH, 256, 0);
    sgemm_tn<<<dim3(512 / 128, MB), thr>>>(tmpm, 256, me_w2, 256, me_b2, x0 + 512,  HH, 256, 0);

    const size_t HSZ = (size_t)BB * HH;   // 65536

    // --- layer 0 ---
    sgemm_tn<<<dim3(H3 / 128, MB), thr>>>(x0, HH, w_ih_l0f, HH, b_ih_l0f, gif, H3, HH, 0);
    sgemm_tn<<<dim3(H3 / 128, MB), thr>>>(x0, HH, w_ih_l0b, HH, b_ih_l0b, gib, H3, HH, 0);
    zero_kernel<<<(4 * (int)HSZ + 255) / 256, 256>>>(hbuf, 4 * (int)HSZ);
    for (int t = 0; t < TT; t++) {
        const float* pf = hbuf + 0 * 2 * HSZ + (size_t)(t & 1) * HSZ;
        const float* pb = hbuf + 1 * 2 * HSZ + (size_t)(t & 1) * HSZ;
        float* nf = hbuf + 0 * 2 * HSZ + (size_t)((t + 1) & 1) * HSZ;
        float* nb = hbuf + 1 * 2 * HSZ + (size_t)((t + 1) & 1) * HSZ;
        gru_step<<<dim3(HH / 16, 2), thr>>>(gif, gib, w_hh_l0f, w_hh_l0b,
                                            b_hh_l0f, b_hh_l0b, pf, pb, nf, nb, y0, t);
    }

    // --- layer 1 ---
    sgemm_tn<<<dim3(H3 / 128, MB), thr>>>(y0, H2, w_ih_l1f, H2, b_ih_l1f, gif, H3, H2, 0);
    sgemm_tn<<<dim3(H3 / 128, MB), thr>>>(y0, H2, w_ih_l1b, H2, b_ih_l1b, gib, H3, H2, 0);
    zero_kernel<<<(4 * (int)HSZ + 255) / 256, 256>>>(hbuf, 4 * (int)HSZ);
    for (int t = 0; t < TT; t++) {
        const float* pf = hbuf + 0 * 2 * HSZ + (size_t)(t & 1) * HSZ;
        const float* pb = hbuf + 1 * 2 * HSZ + (size_t)(t & 1) * HSZ;
        float* nf = hbuf + 0 * 2 * HSZ + (size_t)((t + 1) & 1) * HSZ;
        float* nb = hbuf + 1 * 2 * HSZ + (size_t)((t + 1) & 1) * HSZ;
        gru_step<<<dim3(HH / 16, 2), thr>>>(gif, gib, w_hh_l1f, w_hh_l1b,
                                            b_hh_l1f, b_hh_l1b, pf, pb, nf, nb, y1, t);
    }

    // --- final mean ---
    reduce_mean<<<BB, 256>>>(y1, out);
    (void)in_sizes; (void)n_in; (void)out_size;
}

// round 4
// speedup vs baseline: 1.0820x; 1.0820x over previous
#include <cuda_runtime.h>
#include <cstdio>

// ---------------------------------------------------------------------------
// Problem constants
// ---------------------------------------------------------------------------
#define BB   64
#define TT   300
#define BT   (BB * TT)          // 19200
#define CONDD 64
#define OUTD  72
#define HH   1024
#define H2   2048
#define H3   3072

typedef unsigned long long ull;

// ---------------------------------------------------------------------------
// Device scratch (static globals: allocation-free rule)
// ---------------------------------------------------------------------------
__device__ float g_tmpc[BT * 256];        // cond encoder hidden
__device__ float g_tmpm[BT * 256];        // input encoder hidden
__device__ float g_x0[BT * HH];           // encoder output / layer0 input
__device__ float g_y0[BT * H2];           // layer0 output / layer1 input
__device__ float g_y1[BT * H2];           // layer1 output
__device__ float g_gif[BT * H3];          // gi forward  (reused per layer)
__device__ float g_gib[BT * H3];          // gi backward (reused per layer)
__device__ float g_h[2][2][BB * HH];      // [dir][pingpong][b*H]

// ---------------------------------------------------------------------------
// f32x2 helpers (packed fp32 FMA: 2x FFMA issue throughput)
// ---------------------------------------------------------------------------
__device__ __forceinline__ ull packdup(float x) {
    ull r;
    asm("mov.b64 %0, {%1, %1};" : "=l"(r) : "f"(x));
    return r;
}
__device__ __forceinline__ void fma2(ull &d, ull a, ull b) {
    asm("fma.rn.f32x2 %0, %1, %2, %0;" : "+l"(d) : "l"(a), "l"(b));
}
__device__ __forceinline__ void unpack2(ull v, float &a, float &b) {
    asm("mov.b64 {%0, %1}, %2;" : "=f"(a), "=f"(b) : "l"(v));
}

// ---------------------------------------------------------------------------
// SGEMM:  C[M,N] = A[M,K] @ W[N,K]^T + bias[N]   (optional leaky 0.2)
// BM=128, BN=128, BK=8 double-buffered, 256 threads, 8x8 microtile via f32x2.
// Requires: M % 128 == 0, N % 128 == 0, K % 8 == 0.
// ---------------------------------------------------------------------------
__global__ __launch_bounds__(256, 2)
void sgemm_tn(const float* __restrict__ A, int lda,
              const float* __restrict__ W, int ldw,
              const float* __restrict__ bias,
              float* __restrict__ C, int ldc,
              int K, int leaky)
{
    __shared__ __align__(16) ull   As2[2][8][132];  // A duplicated pairs, [buf][k][m]
    __shared__ __align__(16) float Bs [2][8][132];  // W plain,            [buf][k][n]

    const int tid = threadIdx.x;
    const int ty  = tid >> 4;      // 0..15
    const int tx  = tid & 15;      // 0..15
    const int m0  = blockIdx.y * 128;
    const int n0  = blockIdx.x * 128;

    const int arow  = tid >> 1;    // 0..127
    const int apart = tid & 1;     // which float4 of the 8-wide k slab
    const int ks    = apart * 4;

    const float* Aptr = A + (size_t)(m0 + arow) * lda + apart * 4;
    const float* Wptr = W + (size_t)(n0 + arow) * ldw + apart * 4;

    const int nt = K >> 3;

    ull acc[8][4];
#pragma unroll
    for (int i = 0; i < 8; i++)
#pragma unroll
        for (int j = 0; j < 4; j++) acc[i][j] = 0ull;

    // load tile 0 into regs, stage into buffer 0
    float4 aReg = *(const float4*)Aptr;
    float4 bReg = *(const float4*)Wptr;
    As2[0][ks + 0][arow] = packdup(aReg.x);
    As2[0][ks + 1][arow] = packdup(aReg.y);
    As2[0][ks + 2][arow] = packdup(aReg.z);
    As2[0][ks + 3][arow] = packdup(aReg.w);
    Bs[0][ks + 0][arow] = bReg.x;
    Bs[0][ks + 1][arow] = bReg.y;
    Bs[0][ks + 2][arow] = bReg.z;
    Bs[0][ks + 3][arow] = bReg.w;
    __syncthreads();

    for (int kt = 0; kt < nt; kt++) {
        const int cur = kt & 1;

        // prefetch next tile from global (overlaps with compute below)
        if (kt + 1 < nt) {
            aReg = *(const float4*)(Aptr + (kt + 1) * 8);
            bReg = *(const float4*)(Wptr + (kt + 1) * 8);
        }

#pragma unroll
        for (int k = 0; k < 8; k++) {
            ulonglong2 a01 = *(const ulonglong2*)&As2[cur][k][ty * 4];
            ulonglong2 a23 = *(const ulonglong2*)&As2[cur][k][ty * 4 + 2];
            ulonglong2 a45 = *(const ulonglong2*)&As2[cur][k][64 + ty * 4];
            ulonglong2 a67 = *(const ulonglong2*)&As2[cur][k][64 + ty * 4 + 2];
            ulonglong2 bl  = *(const ulonglong2*)&Bs[cur][k][tx * 4];
            ulonglong2 bh  = *(const ulonglong2*)&Bs[cur][k][64 + tx * 4];

            ull av[8] = {a01.x, a01.y, a23.x, a23.y, a45.x, a45.y, a67.x, a67.y};
            ull bv[4] = {bl.x, bl.y, bh.x, bh.y};
#pragma unroll
            for (int i = 0; i < 8; i++)
#pragma unroll
                for (int j = 0; j < 4; j++)
                    fma2(acc[i][j], av[i], bv[j]);
        }

        // stage next tile into the other buffer
        if (kt + 1 < nt) {
            const int nxt = cur ^ 1;
            As2[nxt][ks + 0][arow] = packdup(aReg.x);
            As2[nxt][ks + 1][arow] = packdup(aReg.y);
            As2[nxt][ks + 2][arow] = packdup(aReg.z);
            As2[nxt][ks + 3][arow] = packdup(aReg.w);
            Bs[nxt][ks + 0][arow] = bReg.x;
            Bs[nxt][ks + 1][arow] = bReg.y;
            Bs[nxt][ks + 2][arow] = bReg.z;
            Bs[nxt][ks + 3][arow] = bReg.w;
        }
        __syncthreads();
    }

    // epilogue: bias + optional leaky, write C
#pragma unroll
    for (int i = 0; i < 8; i++) {
        const int row = m0 + ((i < 4) ? (ty * 4 + i) : (64 + ty * 4 + (i - 4)));
#pragma unroll
        for (int p = 0; p < 4; p++) {
            const int cbase = n0 + ((p < 2) ? (tx * 4 + 2 * p) : (64 + tx * 4 + 2 * (p - 2)));
            float f0, f1;
            unpack2(acc[i][p], f0, f1);
            f0 += bias[cbase];
            f1 += bias[cbase + 1];
            if (leaky) {
                if (f0 < 0.f) f0 *= 0.2f;
                if (f1 < 0.f) f1 *= 0.2f;
            }
            C[(size_t)row * ldc + cbase]     = f0;
            C[(size_t)row * ldc + cbase + 1] = f1;
        }
    }
}

// ---------------------------------------------------------------------------
// One GRU timestep, both directions. grid = (64, 2), 128 threads.
// Thread = (8 batches, 1 hidden col, 3 gates): 12 fma2 per k.
// K tiled by 64 with register prefetch of the next tile's global loads.
// smem traffic per warp per k: h = 2 broadcast LDS.128, W = 3 LDS.64 (~5 cyc)
// vs 24 cyc of fma2 issue -> compute-bound.
// ---------------------------------------------------------------------------
__global__ __launch_bounds__(128)
void gru_step(const float* __restrict__ gi_f, const float* __restrict__ gi_b,
              const float* __restrict__ whh_f, const float* __restrict__ whh_b,
              const float* __restrict__ bhh_f, const float* __restrict__ bhh_b,
              const float* __restrict__ hp_f,  const float* __restrict__ hp_b,
              float* __restrict__ hn_f,        float* __restrict__ hn_b,
              float* __restrict__ y, int t)
{
    const int dir = blockIdx.y;
    const float* gi  = dir ? gi_b  : gi_f;
    const float* whh = dir ? whh_b : whh_f;
    const float* bhh = dir ? bhh_b : bhh_f;
    const float* hp  = dir ? hp_b  : hp_f;
    float*       hn  = dir ? hn_b  : hn_f;
    const int t_eff  = dir ? (TT - 1 - t) : t;
    const int j0     = blockIdx.x * 16;

    __shared__ __align__(16) float Hs[64][68];   // [k][b], b-pairs are f32x2 operands
    __shared__ ull Wd[3][64][17];                // duplicated pairs, [gate][k][col]

    const int tid = threadIdx.x;
    const int col = tid & 15;    // 0..15 -> column j0+col
    const int bg  = tid >> 4;    // 0..7  -> batches bg*8 .. bg*8+7

    ull ar[4], az[4], an[4];
#pragma unroll
    for (int i = 0; i < 4; i++) { ar[i] = 0ull; az[i] = 0ull; an[i] = 0ull; }

    // register prefetch buffers for one 64-k tile
    float4 hv[8];   // h: 1024 float4 per tile / 128 threads = 8 each
    float4 wv[6];   // W: 768 float4 per tile / 128 threads = 6 each

    // ---- load tile 0 into regs ----
#pragma unroll
    for (int r = 0; r < 8; r++) {
        const int s = tid + 128 * r, b = s >> 4, kk = s & 15;
        hv[r] = *(const float4*)&hp[b * HH + kk * 4];
    }
#pragma unroll
    for (int r = 0; r < 6; r++) {
        const int s = tid + 128 * r, g = s >> 8, rr = s & 255, i = rr >> 4, kk = rr & 15;
        wv[r] = *(const float4*)&whh[(size_t)(g * HH + j0 + i) * HH + kk * 4];
    }

    for (int kt = 0; kt < 16; kt++) {
        __syncthreads();   // previous tile's compute readers are done

        // ---- stage regs -> smem ----
#pragma unroll
        for (int r = 0; r < 8; r++) {
            const int s = tid + 128 * r, b = s >> 4, kk = s & 15;
            Hs[kk * 4 + 0][b] = hv[r].x;
            Hs[kk * 4 + 1][b] = hv[r].y;
            Hs[kk * 4 + 2][b] = hv[r].z;
            Hs[kk * 4 + 3][b] = hv[r].w;
        }
#pragma unroll
        for (int r = 0; r < 6; r++) {
            const int s = tid + 128 * r, g = s >> 8, rr = s & 255, i = rr >> 4, kk = rr & 15;
            Wd[g][kk * 4 + 0][i] = packdup(wv[r].x);
            Wd[g][kk * 4 + 1][i] = packdup(wv[r].y);
            Wd[g][kk * 4 + 2][i] = packdup(wv[r].z);
            Wd[g][kk * 4 + 3][i] = packdup(wv[r].w);
        }
        __syncthreads();

        // ---- prefetch next tile from global (hides L2 latency under compute)
        if (kt + 1 < 16) {
            const int k0n = (kt + 1) * 64;
#pragma unroll
            for (int r = 0; r < 8; r++) {
                const int s = tid + 128 * r, b = s >> 4, kk = s & 15;
                hv[r] = *(const float4*)&hp[b * HH + k0n + kk * 4];
            }
#pragma unroll
            for (int r = 0; r < 6; r++) {
                const int s = tid + 128 * r, g = s >> 8, rr = s & 255, i = rr >> 4, kk = rr & 15;
                wv[r] = *(const float4*)&whh[(size_t)(g * HH + j0 + i) * HH + k0n + kk * 4];
            }
        }

        // ---- compute 64 k's ----
#pragma unroll
        for (int k = 0; k < 64; k++) {
            ulonglong2 h01 = *(const ulonglong2*)&Hs[k][bg * 8];
            ulonglong2 h23 = *(const ulonglong2*)&Hs[k][bg * 8 + 4];
            ull wr = Wd[0][k][col];
            ull wz = Wd[1][k][col];
            ull wn = Wd[2][k][col];
            fma2(ar[0], h01.x, wr); fma2(ar[1], h01.y, wr);
            fma2(ar[2], h23.x, wr); fma2(ar[3], h23.y, wr);
            fma2(az[0], h01.x, wz); fma2(az[1], h01.y, wz);
            fma2(az[2], h23.x, wz); fma2(az[3], h23.y, wz);
            fma2(an[0], h01.x, wn); fma2(an[1], h01.y, wn);
            fma2(an[2], h23.x, wn); fma2(an[3], h23.y, wn);
        }
    }

    // ---- gate math + update ----
    const int j = j0 + col;
    const float br = bhh[j], bz = bhh[HH + j], bn = bhh[2 * HH + j];

    float ghr[8], ghz[8], ghn[8];
#pragma unroll
    for (int p = 0; p < 4; p++) {
        unpack2(ar[p], ghr[2 * p], ghr[2 * p + 1]);
        unpack2(az[p], ghz[2 * p], ghz[2 * p + 1]);
        unpack2(an[p], ghn[2 * p], ghn[2 * p + 1]);
    }

#pragma unroll
    for (int i = 0; i < 8; i++) {
        const int b = bg * 8 + i;
        const size_t row = (size_t)b * TT + t_eff;
        const float gir = gi[row * H3 + j];
        const float giz = gi[row * H3 + HH + j];
        const float gin = gi[row * H3 + 2 * HH + j];
        const float r = 1.f / (1.f + expf(-(gir + ghr[i] + br)));
        const float z = 1.f / (1.f + expf(-(giz + ghz[i] + bz)));
        const float n = tanhf(gin + r * (ghn[i] + bn));
        const float hprev = hp[b * HH + j];
        const float h = (1.f - z) * n + z * hprev;
        hn[b * HH + j] = h;
        y[row * H2 + dir * HH + j] = h;
    }
}

// ---------------------------------------------------------------------------
// Utility kernels
// ---------------------------------------------------------------------------
__global__ void zero_kernel(float* a, int n) {
    int i = blockIdx.x * blockDim.x + threadIdx.x;
    if (i < n) a[i] = 0.f;
}

__global__ void reduce_mean(const float* __restrict__ y1, float* __restrict__ out) {
    const int b = blockIdx.x;
    const float4* p = (const float4*)(y1 + (size_t)b * TT * H2);
    const int n4 = TT * H2 / 4;
    float s = 0.f;
    for (int i = threadIdx.x; i < n4; i += blockDim.x) {
        float4 v = p[i];
        s += (v.x + v.y) + (v.z + v.w);
    }
    __shared__ float sm[256];
    sm[threadIdx.x] = s;
    __syncthreads();
    for (int off = 128; off; off >>= 1) {
        if (threadIdx.x < off) sm[threadIdx.x] += sm[threadIdx.x + off];
        __syncthreads();
    }
    if (threadIdx.x == 0) out[b] = sm[0] * (1.f / (TT * (float)H2));
}

// ---------------------------------------------------------------------------
// Launch
// ---------------------------------------------------------------------------
extern "C" void kernel_launch(void* const* d_in, const int* in_sizes, int n_in,
                              void* d_out, int out_size)
{
    const float* cond    = (const float*)d_in[0];
    const float* input   = (const float*)d_in[1];
    const float* ce_w1   = (const float*)d_in[2];
    const float* ce_b1   = (const float*)d_in[3];
    const float* ce_w2   = (const float*)d_in[4];
    const float* ce_b2   = (const float*)d_in[5];
    const float* me_w1   = (const float*)d_in[6];
    const float* me_b1   = (const float*)d_in[7];
    const float* me_w2   = (const float*)d_in[8];
    const float* me_b2   = (const float*)d_in[9];
    const float* w_ih_l0f = (const float*)d_in[10];
    const float* w_hh_l0f = (const float*)d_in[11];
    const float* b_ih_l0f = (const float*)d_in[12];
    const float* b_hh_l0f = (const float*)d_in[13];
    const float* w_ih_l0b = (const float*)d_in[14];
    const float* w_hh_l0b = (const float*)d_in[15];
    const float* b_ih_l0b = (const float*)d_in[16];
    const float* b_hh_l0b = (const float*)d_in[17];
    const float* w_ih_l1f = (const float*)d_in[18];
    const float* w_hh_l1f = (const float*)d_in[19];
    const float* b_ih_l1f = (const float*)d_in[20];
    const float* b_hh_l1f = (const float*)d_in[21];
    const float* w_ih_l1b = (const float*)d_in[22];
    const float* w_hh_l1b = (const float*)d_in[23];
    const float* b_ih_l1b = (const float*)d_in[24];
    const float* b_hh_l1b = (const float*)d_in[25];
    float* out = (float*)d_out;

    float *tmpc, *tmpm, *x0, *y0, *y1, *gif, *gib, *hbuf;
    cudaGetSymbolAddress((void**)&tmpc, g_tmpc);
    cudaGetSymbolAddress((void**)&tmpm, g_tmpm);
    cudaGetSymbolAddress((void**)&x0,   g_x0);
    cudaGetSymbolAddress((void**)&y0,   g_y0);
    cudaGetSymbolAddress((void**)&y1,   g_y1);
    cudaGetSymbolAddress((void**)&gif,  g_gif);
    cudaGetSymbolAddress((void**)&gib,  g_gib);
    cudaGetSymbolAddress((void**)&hbuf, g_h);

    const dim3 thr256(256);
    const int MB = BT / 128;   // 150 m-blocks

    // --- encoders ---
    sgemm_tn<<<dim3(256 / 128, MB), thr256>>>(cond,  CONDD, ce_w1, CONDD, ce_b1, tmpc, 256, CONDD, 1);
    sgemm_tn<<<dim3(256 / 128, MB), thr256>>>(input, OUTD,  me_w1, OUTD,  me_b1, tmpm, 256, OUTD,  1);
    sgemm_tn<<<dim3(512 / 128, MB), thr256>>>(tmpc, 256, ce_w2, 256, ce_b2, x0,        HH, 256, 0);
    sgemm_tn<<<dim3(512 / 128, MB), thr256>>>(tmpm, 256, me_w2, 256, me_b2, x0 + 512,  HH, 256, 0);

    const size_t HSZ = (size_t)BB * HH;   // 65536

    // --- layer 0 ---
    sgemm_tn<<<dim3(H3 / 128, MB), thr256>>>(x0, HH, w_ih_l0f, HH, b_ih_l0f, gif, H3, HH, 0);
    sgemm_tn<<<dim3(H3 / 128, MB), thr256>>>(x0, HH, w_ih_l0b, HH, b_ih_l0b, gib, H3, HH, 0);
    zero_kernel<<<(4 * (int)HSZ + 255) / 256, 256>>>(hbuf, 4 * (int)HSZ);
    for (int t = 0; t < TT; t++) {
        const float* pf = hbuf + 0 * 2 * HSZ + (size_t)(t & 1) * HSZ;
        const float* pb = hbuf + 1 * 2 * HSZ + (size_t)(t & 1) * HSZ;
        float* nf = hbuf + 0 * 2 * HSZ + (size_t)((t + 1) & 1) * HSZ;
        float* nb = hbuf + 1 * 2 * HSZ + (size_t)((t + 1) & 1) * HSZ;
        gru_step<<<dim3(HH / 16, 2), 128>>>(gif, gib, w_hh_l0f, w_hh_l0b,
                                            b_hh_l0f, b_hh_l0b, pf, pb, nf, nb, y0, t);
    }

    // --- layer 1 ---
    sgemm_tn<<<dim3(H3 / 128, MB), thr256>>>(y0, H2, w_ih_l1f, H2, b_ih_l1f, gif, H3, H2, 0);
    sgemm_tn<<<dim3(H3 / 128, MB), thr256>>>(y0, H2, w_ih_l1b, H2, b_ih_l1b, gib, H3, H2, 0);
    zero_kernel<<<(4 * (int)HSZ + 255) / 256, 256>>>(hbuf, 4 * (int)HSZ);
    for (int t = 0; t < TT; t++) {
        const float* pf = hbuf + 0 * 2 * HSZ + (size_t)(t & 1) * HSZ;
        const float* pb = hbuf + 1 * 2 * HSZ + (size_t)(t & 1) * HSZ;
        float* nf = hbuf + 0 * 2 * HSZ + (size_t)((t + 1) & 1) * HSZ;
        float* nb = hbuf + 1 * 2 * HSZ + (size_t)((t + 1) & 1) * HSZ;
        gru_step<<<dim3(HH / 16, 2), 128>>>(gif, gib, w_hh_l1f, w_hh_l1b,
                                            b_hh_l1f, b_hh_l1b, pf, pb, nf, nb, y1, t);
    }

    // --- final mean ---
    reduce_mean<<<BB, 256>>>(y1, out);
    (void)in_sizes; (void)n_in; (void)out_size;
}